// round 1
// baseline (speedup 1.0000x reference)
#include <cuda_runtime.h>
#include <cstdint>

// Problem constants
constexpr int B = 2;
constexpr int D = 64;
constexpr int HH = 96;
constexpr int WW = 96;
constexpr int N = HH * WW;      // 9216
constexpr int ITERS = 4;
constexpr float KBW = 0.3f;
constexpr float STEP = 0.5f;

// Tiling
constexpr int BM = 128;          // output columns (m points) per block
constexpr int BN = 128;          // n-tile size
constexpr int THREADS = 256;
constexpr int NTILES_M = N / BM; // 72

// Shared memory layout (floats): sXm[D][BM] | sXn[D][BN] | sK[BN][BM] | sDen[BM]
constexpr int SXM_OFF = 0;
constexpr int SXN_OFF = D * BM;                 // 8192
constexpr int SK_OFF  = SXN_OFF + D * BN;       // 16384
constexpr int SDEN_OFF = SK_OFF + BN * BM;      // 32768
constexpr int SMEM_FLOATS = SDEN_OFF + BM;      // 32896
constexpr int SMEM_BYTES = SMEM_FLOATS * 4;     // 131584

// exp(KBW * s) via fma-pipe polynomial: 2^(s*KBW*log2e) = 2^i * 2^f
__device__ __forceinline__ float expk(float s) {
    const float C = KBW * 1.4426950408889634f;
    float t = s * C;
    t = fminf(fmaxf(t, -120.0f), 120.0f);       // keep exponent splice valid
    float r = t + 12582912.0f;                   // round-to-nearest via 1.5*2^23
    int ii = __float_as_int(r) - 0x4B400000;     // integer part
    float f = t - (r - 12582912.0f);             // f in [-0.5, 0.5]
    float p = 1.3333558146428443e-3f;
    p = fmaf(p, f, 9.618129107628477e-3f);
    p = fmaf(p, f, 5.550410866482158e-2f);
    p = fmaf(p, f, 2.402265069591007e-1f);
    p = fmaf(p, f, 6.931471805599453e-1f);
    p = fmaf(p, f, 1.0f);
    return __int_as_float(__float_as_int(p) + (ii << 23));
}

// Copy x_in (B, D, N) into output slice i=0 of (B, ITERS+1, D, N)
__global__ void copy_x0_kernel(const float* __restrict__ x, float* __restrict__ out) {
    int i = blockIdx.x * blockDim.x + threadIdx.x;
    int total = B * D * N / 4;
    if (i < total) {
        int perb = D * N / 4;
        int b = i / perb;
        int r = i - b * perb;
        float4 v = ((const float4*)x)[i];
        ((float4*)out)[(size_t)b * ((ITERS + 1) * D * N / 4) + r] = v;
    }
}

// One mean-shift iteration: reads slice `it`, writes slice `it+1`.
__global__ __launch_bounds__(THREADS, 1)
void ms_iter_kernel(float* __restrict__ out, int it) {
    extern __shared__ float sm[];
    float* sXm = sm + SXM_OFF;   // [D][BM]
    float* sXn = sm + SXN_OFF;   // [D][BN]
    float* sK  = sm + SK_OFF;    // [BN][BM]
    float* sDen = sm + SDEN_OFF; // [BM]

    const int b = blockIdx.y;
    const int m0 = blockIdx.x * BM;
    const float* __restrict__ xin = out + ((size_t)b * (ITERS + 1) + it) * (size_t)(D * N);
    float* __restrict__ xout = out + ((size_t)b * (ITERS + 1) + it + 1) * (size_t)(D * N);

    const int tid = threadIdx.x;
    const int lane = tid & 31;
    const int wid = tid >> 5;

    // Load Xm tile (stays resident whole kernel)
    #pragma unroll
    for (int r = 0; r < 8; ++r) {
        int d = r * 8 + wid;
        float4 v = *(const float4*)(xin + (size_t)d * N + m0 + lane * 4);
        *(float4*)(sXm + d * BM + lane * 4) = v;
    }

    // S-GEMM mapping: 16(m-groups) x 16(n-groups), 8x8 microtile
    const int tm = tid & 15;
    const int tn = tid >> 4;
    // O-GEMM mapping: 16(m-groups) x 16(d-groups), 4(d)x8(m) microtile
    const int tm2 = tid & 15;
    const int td = tid >> 4;

    float oacc[4][8];
    #pragma unroll
    for (int i = 0; i < 4; ++i)
        #pragma unroll
        for (int j = 0; j < 8; ++j) oacc[i][j] = 0.0f;

    float dpart[8];
    #pragma unroll
    for (int j = 0; j < 8; ++j) dpart[j] = 0.0f;

    for (int n0 = 0; n0 < N; n0 += BN) {
        // Load Xn tile
        #pragma unroll
        for (int r = 0; r < 8; ++r) {
            int d = r * 8 + wid;
            float4 v = *(const float4*)(xin + (size_t)d * N + n0 + lane * 4);
            *(float4*)(sXn + d * BN + lane * 4) = v;
        }
        __syncthreads();

        // ---- S = Xn^T Xm (128x128, depth 64), 8x8 per thread ----
        float acc[8][8];
        #pragma unroll
        for (int i = 0; i < 8; ++i)
            #pragma unroll
            for (int j = 0; j < 8; ++j) acc[i][j] = 0.0f;

        #pragma unroll 4
        for (int k = 0; k < D; ++k) {
            float4 b0 = *(const float4*)(sXm + k * BM + tm * 8);
            float4 b1 = *(const float4*)(sXm + k * BM + tm * 8 + 4);
            float4 a0 = *(const float4*)(sXn + k * BN + tn * 8);
            float4 a1 = *(const float4*)(sXn + k * BN + tn * 8 + 4);
            float av[8] = {a0.x, a0.y, a0.z, a0.w, a1.x, a1.y, a1.z, a1.w};
            float bv[8] = {b0.x, b0.y, b0.z, b0.w, b1.x, b1.y, b1.z, b1.w};
            #pragma unroll
            for (int i = 0; i < 8; ++i)
                #pragma unroll
                for (int j = 0; j < 8; ++j)
                    acc[i][j] = fmaf(av[i], bv[j], acc[i][j]);
        }

        // ---- K = exp(KBW*S), accumulate column partial sums, store K tile ----
        #pragma unroll
        for (int i = 0; i < 8; ++i) {
            float kv[8];
            #pragma unroll
            for (int j = 0; j < 8; ++j) {
                kv[j] = expk(acc[i][j]);
                dpart[j] += kv[j];
            }
            float* dst = sK + (tn * 8 + i) * BM + tm * 8;
            *(float4*)(dst)     = make_float4(kv[0], kv[1], kv[2], kv[3]);
            *(float4*)(dst + 4) = make_float4(kv[4], kv[5], kv[6], kv[7]);
        }
        __syncthreads();

        // ---- O += Xn * K (64x128, depth 128), 4x8 per thread ----
        for (int n = 0; n < BN; n += 4) {
            float4 xr[4];
            #pragma unroll
            for (int dd = 0; dd < 4; ++dd)
                xr[dd] = *(const float4*)(sXn + (td * 4 + dd) * BN + n);
            #pragma unroll
            for (int jn = 0; jn < 4; ++jn) {
                const float* krow = sK + (n + jn) * BM + tm2 * 8;
                float4 k0 = *(const float4*)(krow);
                float4 k1 = *(const float4*)(krow + 4);
                float kb[8] = {k0.x, k0.y, k0.z, k0.w, k1.x, k1.y, k1.z, k1.w};
                #pragma unroll
                for (int dd = 0; dd < 4; ++dd) {
                    float a = (jn == 0) ? xr[dd].x : (jn == 1) ? xr[dd].y
                            : (jn == 2) ? xr[dd].z : xr[dd].w;
                    #pragma unroll
                    for (int mm = 0; mm < 8; ++mm)
                        oacc[dd][mm] = fmaf(a, kb[mm], oacc[dd][mm]);
                }
            }
        }
        __syncthreads();  // before next tile overwrites sXn / sK
    }

    // ---- Reduce column sums: 16 n-group partials per m ----
    float* sRed = sK;  // reuse K region (16 x BM)
    #pragma unroll
    for (int j = 0; j < 8; ++j)
        sRed[tn * BM + tm * 8 + j] = dpart[j];
    __syncthreads();
    if (tid < BM) {
        float s = 0.0f;
        #pragma unroll
        for (int g = 0; g < 16; ++g) s += sRed[g * BM + tid];
        sDen[tid] = s;
    }
    __syncthreads();

    // ---- Epilogue: x_new = STEP * O/den + (1-STEP) * x ----
    #pragma unroll
    for (int dd = 0; dd < 4; ++dd) {
        int d = td * 4 + dd;
        float v[8];
        #pragma unroll
        for (int mm = 0; mm < 8; ++mm) {
            int m = tm2 * 8 + mm;
            float den = sDen[m];
            v[mm] = fmaf(STEP, oacc[dd][mm] / den, (1.0f - STEP) * sXm[d * BM + m]);
        }
        float* dst = xout + (size_t)d * N + m0 + tm2 * 8;
        *(float4*)(dst)     = make_float4(v[0], v[1], v[2], v[3]);
        *(float4*)(dst + 4) = make_float4(v[4], v[5], v[6], v[7]);
    }
}

extern "C" void kernel_launch(void* const* d_in, const int* in_sizes, int n_in,
                              void* d_out, int out_size) {
    const float* x = (const float*)d_in[0];
    float* out = (float*)d_out;

    cudaFuncSetAttribute(ms_iter_kernel,
                         cudaFuncAttributeMaxDynamicSharedMemorySize, SMEM_BYTES);

    int copy_total = B * D * N / 4;
    copy_x0_kernel<<<(copy_total + 255) / 256, 256>>>(x, out);

    dim3 grid(NTILES_M, B);
    for (int it = 0; it < ITERS; ++it)
        ms_iter_kernel<<<grid, THREADS, SMEM_BYTES>>>(out, it);
}

// round 3
// speedup vs baseline: 2.6569x; 2.6569x over previous
#include <cuda_runtime.h>
#include <cuda_bf16.h>
#include <cstdint>

// ---------------- problem constants ----------------
constexpr int B = 2;
constexpr int D = 64;
constexpr int N = 96 * 96;      // 9216
constexpr int ITERS = 4;
constexpr float STEP = 0.5f;
constexpr float KBW = 0.3f;

constexpr int BM = 128;
constexpr int BN = 128;
constexpr int THREADS = 256;
constexpr int NT = N / BN;      // 72
constexpr int NTM = N / BM;     // 72

// ---------------- smem layout (bytes) ----------------
// XM/XN: 2 chunks of [64 d][64 pt] bf16, 128B rows (8KB per chunk)
// KT:    2 chunks of [128 m][64 n] bf16, 128B rows (16KB per chunk)
constexpr int XM_H = 0;
constexpr int XM_L = XM_H + 16384;
constexpr int XN_H = XM_L + 16384;
constexpr int XN_L = XN_H + 16384;
constexpr int KT_H = XN_L + 16384;
constexpr int KT_L = KT_H + 32768;
constexpr int SDEN = KT_L + 32768;            // 2 x 128 f32
constexpr int SMEM_BYTES = SDEN + 1024;       // 132 KB
// sOut f32 [64][132] reuses KT_H.. region (33792 B)

// ---------------- helpers ----------------
__device__ __forceinline__ uint32_t smem_u32(const void* p) {
    uint32_t a;
    asm("{ .reg .u64 t; cvta.to.shared.u64 t, %1; cvt.u32.u64 %0, t; }"
        : "=r"(a) : "l"(p));
    return a;
}

__device__ __forceinline__ uint32_t swz(uint32_t o) {
    return o ^ ((o >> 3) & 0x70);
}

#define LDSM_X4(r, addr)                                                     \
    asm volatile("ldmatrix.sync.aligned.m8n8.x4.shared.b16 {%0,%1,%2,%3}, [%4];" \
        : "=r"((r)[0]), "=r"((r)[1]), "=r"((r)[2]), "=r"((r)[3]) : "r"(addr))

#define LDSM_X4_T(r, addr)                                                   \
    asm volatile("ldmatrix.sync.aligned.m8n8.x4.trans.shared.b16 {%0,%1,%2,%3}, [%4];" \
        : "=r"((r)[0]), "=r"((r)[1]), "=r"((r)[2]), "=r"((r)[3]) : "r"(addr))

#define STS128(addr, p)                                                      \
    asm volatile("st.shared.v4.b32 [%0], {%1, %2, %3, %4};"                  \
        :: "r"(addr), "r"((p)[0]), "r"((p)[1]), "r"((p)[2]), "r"((p)[3]) : "memory")

#define STS32(addr, v)                                                       \
    asm volatile("st.shared.b32 [%0], %1;" :: "r"(addr), "r"(v) : "memory")

__device__ __forceinline__ void hmma(float* c, const uint32_t* a, const uint32_t* b) {
    asm volatile(
        "mma.sync.aligned.m16n8k16.row.col.f32.bf16.bf16.f32 "
        "{%0,%1,%2,%3}, {%4,%5,%6,%7}, {%8,%9}, {%0,%1,%2,%3};"
        : "+f"(c[0]), "+f"(c[1]), "+f"(c[2]), "+f"(c[3])
        : "r"(a[0]), "r"(a[1]), "r"(a[2]), "r"(a[3]), "r"(b[0]), "r"(b[1]));
}

__device__ __forceinline__ uint32_t pack2(__nv_bfloat16 a, __nv_bfloat16 b) {
    return (uint32_t)__bfloat16_as_ushort(a) |
           ((uint32_t)__bfloat16_as_ushort(b) << 16);
}

__device__ __forceinline__ void split_pair(float v0, float v1,
                                           uint32_t& hw, uint32_t& lw) {
    __nv_bfloat16 h0 = __float2bfloat16_rn(v0);
    __nv_bfloat16 h1 = __float2bfloat16_rn(v1);
    __nv_bfloat16 l0 = __float2bfloat16_rn(v0 - __bfloat162float(h0));
    __nv_bfloat16 l1 = __float2bfloat16_rn(v1 - __bfloat162float(h1));
    hw = pack2(h0, h1);
    lw = pack2(l0, l1);
}

// exp(KBW * s): fma-pipe polynomial 2^t with exponent splice
__device__ __forceinline__ float expk(float s) {
    const float C = KBW * 1.4426950408889634f;
    float t = s * C;
    t = fminf(fmaxf(t, -120.0f), 120.0f);
    float r = t + 12582912.0f;
    int ii = __float_as_int(r) - 0x4B400000;
    float f = t - (r - 12582912.0f);
    float p = 1.3333558146428443e-3f;
    p = fmaf(p, f, 9.618129107628477e-3f);
    p = fmaf(p, f, 5.550410866482158e-2f);
    p = fmaf(p, f, 2.402265069591007e-1f);
    p = fmaf(p, f, 6.931471805599453e-1f);
    p = fmaf(p, f, 1.0f);
    return __int_as_float(__float_as_int(p) + (ii << 23));
}

// Copy x_in (B, D, N) into output slice i=0 of (B, ITERS+1, D, N)
__global__ void copy_x0_kernel(const float* __restrict__ x, float* __restrict__ out) {
    int i = blockIdx.x * blockDim.x + threadIdx.x;
    int total = B * D * N / 4;
    if (i < total) {
        int perb = D * N / 4;
        int b = i / perb;
        int r = i - b * perb;
        float4 v = ((const float4*)x)[i];
        ((float4*)out)[(size_t)b * ((ITERS + 1) * D * N / 4) + r] = v;
    }
}

// Build hi/lo bf16 natural-layout tile: 2 chunks [64 d][64 pt], SW128 rows.
__device__ __forceinline__ void build_x(uint32_t sb, uint32_t offH, uint32_t offL,
                                        const float* __restrict__ src, int p0, int tid) {
    #pragma unroll
    for (int q = 0; q < 4; ++q) {
        int task = q * 256 + tid;         // d(64) x g(16)
        int d = task >> 4, g = task & 15;
        const float4* s = (const float4*)(src + (size_t)d * N + p0 + g * 8);
        float4 v0 = s[0], v1 = s[1];
        uint32_t hp[4], lp[4];
        split_pair(v0.x, v0.y, hp[0], lp[0]);
        split_pair(v0.z, v0.w, hp[1], lp[1]);
        split_pair(v1.x, v1.y, hp[2], lp[2]);
        split_pair(v1.z, v1.w, hp[3], lp[3]);
        uint32_t off = swz((uint32_t)(d * 128 + (g & 7) * 16)) + (g >> 3) * 8192;
        STS128(sb + offH + off, hp);
        STS128(sb + offL + off, lp);
    }
}

// ---------------- main kernel ----------------
__global__ __launch_bounds__(THREADS, 1)
void ms_mma_kernel(float* __restrict__ out, int it) {
    extern __shared__ unsigned char smc[];
    uint32_t sb = smem_u32(smc);

    const int tid = threadIdx.x;
    const int l = tid & 31;
    const int w = tid >> 5;
    const int wm = w & 3;        // m group (32 rows)
    const int wn = w >> 2;       // n group (64 cols) for MMA1; dd group for MMA2

    const int b = blockIdx.y;
    const int m0 = blockIdx.x * BM;
    const float* __restrict__ xin = out + ((size_t)b * (ITERS + 1) + it) * (size_t)(D * N);
    float* __restrict__ xout = (float*)xin + (size_t)D * N;

    // lane-derived fragment address components
    const int l7 = l & 7, l8 = l & 8, l16h = (l & 16) >> 1, lq = l >> 2, lr = l & 3;

    // resident Xm tile (natural layout, hi/lo)
    build_x(sb, XM_H, XM_L, xin, m0, tid);

    float accO[2][4][4];
    #pragma unroll
    for (int i = 0; i < 2; ++i)
        #pragma unroll
        for (int j = 0; j < 4; ++j)
            #pragma unroll
            for (int c = 0; c < 4; ++c) accO[i][j][c] = 0.0f;

    float dsum[2][2] = {{0.0f, 0.0f}, {0.0f, 0.0f}};

    for (int t = 0; t < NT; ++t) {
        build_x(sb, XN_H, XN_L, xin, t * BN, tid);
        __syncthreads();

        // ---- MMA1: S[32m x 64n] per warp, k = 64 d, 3 split passes ----
        float accS[2][8][4];
        #pragma unroll
        for (int i = 0; i < 2; ++i)
            #pragma unroll
            for (int j = 0; j < 8; ++j)
                #pragma unroll
                for (int c = 0; c < 4; ++c) accS[i][j][c] = 0.0f;

        #pragma unroll
        for (int k = 0; k < 4; ++k) {
            const int kb = k * 16;
            uint32_t Ah[2][4], Al[2][4];
            #pragma unroll
            for (int mi = 0; mi < 2; ++mi) {
                int drow = kb + l7 + l16h;
                int mcol = (wm & 1) * 32 + mi * 16 + l8;
                uint32_t off = swz((uint32_t)(drow * 128 + mcol * 2)) + (wm >> 1) * 8192;
                LDSM_X4_T(Ah[mi], sb + XM_H + off);
                LDSM_X4_T(Al[mi], sb + XM_L + off);
            }
            #pragma unroll
            for (int p = 0; p < 4; ++p) {
                uint32_t Bh[4], Bl[4];
                int drow = kb + l7 + l8;
                int ncol = p * 16 + l16h;
                uint32_t off = swz((uint32_t)(drow * 128 + ncol * 2)) + wn * 8192;
                LDSM_X4_T(Bh, sb + XN_H + off);
                LDSM_X4_T(Bl, sb + XN_L + off);
                #pragma unroll
                for (int mi = 0; mi < 2; ++mi) {
                    hmma(accS[mi][2 * p],     Ah[mi], Bh);
                    hmma(accS[mi][2 * p + 1], Ah[mi], Bh + 2);
                    hmma(accS[mi][2 * p],     Ah[mi], Bl);
                    hmma(accS[mi][2 * p + 1], Ah[mi], Bl + 2);
                    hmma(accS[mi][2 * p],     Al[mi], Bh);
                    hmma(accS[mi][2 * p + 1], Al[mi], Bh + 2);
                }
            }
        }

        // ---- K = exp(KBW*S): den accumulation + K^T hi/lo to smem ----
        #pragma unroll
        for (int mi = 0; mi < 2; ++mi) {
            const int m = wm * 32 + mi * 16 + lq;
            #pragma unroll
            for (int nj = 0; nj < 8; ++nj) {
                float e0 = expk(accS[mi][nj][0]);
                float e1 = expk(accS[mi][nj][1]);
                float e2 = expk(accS[mi][nj][2]);
                float e3 = expk(accS[mi][nj][3]);
                dsum[mi][0] += e0 + e1;
                dsum[mi][1] += e2 + e3;
                uint32_t h01, l01, h23, l23;
                split_pair(e0, e1, h01, l01);
                split_pair(e2, e3, h23, l23);
                int nn = nj * 8 + 2 * lr;
                uint32_t o1 = swz((uint32_t)(m * 128 + nn * 2)) + wn * 16384;
                uint32_t o2 = swz((uint32_t)((m + 8) * 128 + nn * 2)) + wn * 16384;
                STS32(sb + KT_H + o1, h01);
                STS32(sb + KT_L + o1, l01);
                STS32(sb + KT_H + o2, h23);
                STS32(sb + KT_L + o2, l23);
            }
        }
        __syncthreads();

        // ---- MMA2: O[32m x 32dd] per warp += K^T . Xn, k = 128 n ----
        #pragma unroll
        for (int ks = 0; ks < 8; ++ks) {
            const int ch = ks >> 2;
            const int kb = (ks & 3) * 16;
            uint32_t Ah[2][4], Al[2][4];
            #pragma unroll
            for (int mi = 0; mi < 2; ++mi) {
                int m = wm * 32 + mi * 16 + (l & 15);
                int nn = kb + l16h;
                uint32_t off = swz((uint32_t)(m * 128 + nn * 2)) + ch * 16384;
                LDSM_X4(Ah[mi], sb + KT_H + off);
                LDSM_X4(Al[mi], sb + KT_L + off);
            }
            uint32_t Bh[2][4], Bl[2][4];
            #pragma unroll
            for (int dp = 0; dp < 2; ++dp) {
                int dd = wn * 32 + dp * 16 + l7 + l16h;
                int nn = kb + l8;
                uint32_t off = swz((uint32_t)(dd * 128 + nn * 2)) + ch * 8192;
                LDSM_X4(Bh[dp], sb + XN_H + off);
                LDSM_X4(Bl[dp], sb + XN_L + off);
            }
            #pragma unroll
            for (int mi = 0; mi < 2; ++mi)
                #pragma unroll
                for (int dp = 0; dp < 2; ++dp) {
                    hmma(accO[mi][2 * dp],     Ah[mi], Bh[dp]);
                    hmma(accO[mi][2 * dp + 1], Ah[mi], Bh[dp] + 2);
                    hmma(accO[mi][2 * dp],     Ah[mi], Bl[dp]);
                    hmma(accO[mi][2 * dp + 1], Ah[mi], Bl[dp] + 2);
                    hmma(accO[mi][2 * dp],     Al[mi], Bh[dp]);
                    hmma(accO[mi][2 * dp + 1], Al[mi], Bh[dp] + 2);
                }
        }
        __syncthreads();   // before next tile's build overwrites XN / KT
    }

    // ---- reduce den: shfl over 4 lanes sharing a row, then across wn ----
    float* sDen = (float*)(smc + (SDEN - 0)) ;
    #pragma unroll
    for (int mi = 0; mi < 2; ++mi)
        #pragma unroll
        for (int h = 0; h < 2; ++h) {
            float v = dsum[mi][h];
            v += __shfl_xor_sync(0xFFFFFFFFu, v, 1);
            v += __shfl_xor_sync(0xFFFFFFFFu, v, 2);
            if (lr == 0)
                sDen[wn * 128 + wm * 32 + mi * 16 + h * 8 + lq] = v;
        }
    __syncthreads();

    // ---- O epilogue: scale by STEP/den, transpose via smem, write out ----
    float* sO = (float*)(smc + KT_H);   // [64 dd][132 m] f32, reuses KT
    float sc[2][2];
    #pragma unroll
    for (int mi = 0; mi < 2; ++mi)
        #pragma unroll
        for (int h = 0; h < 2; ++h) {
            int m = wm * 32 + mi * 16 + h * 8 + lq;
            sc[mi][h] = STEP / (sDen[m] + sDen[128 + m]);
        }
    #pragma unroll
    for (int mi = 0; mi < 2; ++mi) {
        int m = wm * 32 + mi * 16 + lq;
        #pragma unroll
        for (int dj = 0; dj < 4; ++dj) {
            int dd = wn * 32 + dj * 8 + 2 * lr;
            sO[dd * 132 + m]           = accO[mi][dj][0] * sc[mi][0];
            sO[(dd + 1) * 132 + m]     = accO[mi][dj][1] * sc[mi][0];
            sO[dd * 132 + m + 8]       = accO[mi][dj][2] * sc[mi][1];
            sO[(dd + 1) * 132 + m + 8] = accO[mi][dj][3] * sc[mi][1];
        }
    }
    __syncthreads();

    #pragma unroll
    for (int q = 0; q < 8; ++q) {
        int task = q * 256 + tid;       // dd(64) x mq(32)
        int dd = task >> 5, mq = task & 31;
        float4 o = *(float4*)&sO[dd * 132 + mq * 4];
        float4 x = *(const float4*)(xin + (size_t)dd * N + m0 + mq * 4);
        float4 r;
        r.x = fmaf(1.0f - STEP, x.x, o.x);
        r.y = fmaf(1.0f - STEP, x.y, o.y);
        r.z = fmaf(1.0f - STEP, x.z, o.z);
        r.w = fmaf(1.0f - STEP, x.w, o.w);
        *(float4*)(xout + (size_t)dd * N + m0 + mq * 4) = r;
    }
}

extern "C" void kernel_launch(void* const* d_in, const int* in_sizes, int n_in,
                              void* d_out, int out_size) {
    const float* x = (const float*)d_in[0];
    float* out = (float*)d_out;

    cudaFuncSetAttribute(ms_mma_kernel,
                         cudaFuncAttributeMaxDynamicSharedMemorySize, SMEM_BYTES);

    int copy_total = B * D * N / 4;
    copy_x0_kernel<<<(copy_total + 255) / 256, 256>>>(x, out);

    dim3 grid(NTM, B);
    for (int it = 0; it < ITERS; ++it)
        ms_mma_kernel<<<grid, THREADS, SMEM_BYTES>>>(out, it);
}

// round 4
// speedup vs baseline: 3.1313x; 1.1786x over previous
#include <cuda_runtime.h>
#include <cuda_bf16.h>
#include <cstdint>

// ---------------- problem constants ----------------
constexpr int B = 2;
constexpr int D = 64;
constexpr int N = 96 * 96;      // 9216
constexpr int ITERS = 4;
constexpr float STEP = 0.5f;
constexpr float KBW = 0.3f;

constexpr int BM = 128;
constexpr int BN = 128;
constexpr int THREADS = 512;
constexpr int NT = N / BN;      // 72

// Tile image: 2 chunks x [64 d][64 pt] bf16, 128B swizzled rows = 16384 B
constexpr int IMG = 16384;

// ---------------- device-global converted operand buffers ----------------
__device__ __align__(16) unsigned char g_xh[(size_t)B * NT * IMG];  // hi bf16 images
__device__ __align__(16) unsigned char g_xl[(size_t)B * NT * IMG];  // lo bf16 images

// ---------------- smem layout (bytes) ----------------
constexpr int XM_H = 0;                  // 16 KB
constexpr int XM_L = 16384;
constexpr int XN_BASE0 = 32768;          // buf0: H at +0, L at +16384
constexpr int XN_BASE1 = 65536;          // buf1
constexpr int KT_H = 98304;              // 2 chunks x [128 m][64 n] = 32 KB
constexpr int KT_L = 131072;
constexpr int SDEN = 163840;             // 4 x 128 f32
constexpr int SMEM_BYTES = SDEN + 2048;  // 165888
// sO f32 [64][132] reuses KT_H region in final epilogue

// ---------------- asm helpers ----------------
__device__ __forceinline__ uint32_t smem_u32(const void* p) {
    uint32_t a;
    asm("{ .reg .u64 t; cvta.to.shared.u64 t, %1; cvt.u32.u64 %0, t; }"
        : "=r"(a) : "l"(p));
    return a;
}

__device__ __forceinline__ uint32_t swz(uint32_t o) {
    return o ^ ((o >> 3) & 0x70);
}

__device__ __forceinline__ void cp16(uint32_t s, const void* g) {
    asm volatile("cp.async.cg.shared.global [%0], [%1], 16;"
                 :: "r"(s), "l"(__cvta_generic_to_global(g)) : "memory");
}
#define CP_COMMIT() asm volatile("cp.async.commit_group;" ::: "memory")
#define CP_WAIT1()  asm volatile("cp.async.wait_group 1;" ::: "memory")
#define CP_WAIT0()  asm volatile("cp.async.wait_group 0;" ::: "memory")

#define LDSM_X4(r, addr)                                                     \
    asm volatile("ldmatrix.sync.aligned.m8n8.x4.shared.b16 {%0,%1,%2,%3}, [%4];" \
        : "=r"((r)[0]), "=r"((r)[1]), "=r"((r)[2]), "=r"((r)[3]) : "r"(addr))

#define LDSM_X4_T(r, addr)                                                   \
    asm volatile("ldmatrix.sync.aligned.m8n8.x4.trans.shared.b16 {%0,%1,%2,%3}, [%4];" \
        : "=r"((r)[0]), "=r"((r)[1]), "=r"((r)[2]), "=r"((r)[3]) : "r"(addr))

#define STS32(addr, v)                                                       \
    asm volatile("st.shared.b32 [%0], %1;" :: "r"(addr), "r"(v) : "memory")

__device__ __forceinline__ void hmma(float* c, const uint32_t* a, const uint32_t* b) {
    asm volatile(
        "mma.sync.aligned.m16n8k16.row.col.f32.bf16.bf16.f32 "
        "{%0,%1,%2,%3}, {%4,%5,%6,%7}, {%8,%9}, {%0,%1,%2,%3};"
        : "+f"(c[0]), "+f"(c[1]), "+f"(c[2]), "+f"(c[3])
        : "r"(a[0]), "r"(a[1]), "r"(a[2]), "r"(a[3]), "r"(b[0]), "r"(b[1]));
}

__device__ __forceinline__ uint32_t pack2(__nv_bfloat16 a, __nv_bfloat16 b) {
    return (uint32_t)__bfloat16_as_ushort(a) |
           ((uint32_t)__bfloat16_as_ushort(b) << 16);
}

__device__ __forceinline__ void split_pair(float v0, float v1,
                                           uint32_t& hw, uint32_t& lw) {
    __nv_bfloat16 h0 = __float2bfloat16_rn(v0);
    __nv_bfloat16 h1 = __float2bfloat16_rn(v1);
    __nv_bfloat16 l0 = __float2bfloat16_rn(v0 - __bfloat162float(h0));
    __nv_bfloat16 l1 = __float2bfloat16_rn(v1 - __bfloat162float(h1));
    hw = pack2(h0, h1);
    lw = pack2(l0, l1);
}

// exp(KBW*s): fma-pipe polynomial 2^t with exponent splice (no clamp; |t|<60)
__device__ __forceinline__ float expk(float s) {
    const float C = KBW * 1.4426950408889634f;
    float t = s * C;
    float r = t + 12582912.0f;
    int ii = __float_as_int(r) - 0x4B400000;
    float f = t - (r - 12582912.0f);
    float p = 1.3333558146428443e-3f;
    p = fmaf(p, f, 9.618129107628477e-3f);
    p = fmaf(p, f, 5.550410866482158e-2f);
    p = fmaf(p, f, 2.402265069591007e-1f);
    p = fmaf(p, f, 6.931471805599453e-1f);
    p = fmaf(p, f, 1.0f);
    return __int_as_float(__float_as_int(p) + (ii << 23));
}

// Copy x_in (B, D, N) into output slice i=0 of (B, ITERS+1, D, N)
__global__ void copy_x0_kernel(const float* __restrict__ x, float* __restrict__ out) {
    int i = blockIdx.x * blockDim.x + threadIdx.x;
    int total = B * D * N / 4;
    if (i < total) {
        int perb = D * N / 4;
        int b = i / perb;
        int r = i - b * perb;
        float4 v = ((const float4*)x)[i];
        ((float4*)out)[(size_t)b * ((ITERS + 1) * D * N / 4) + r] = v;
    }
}

// Convert x slice `it` into hi/lo bf16 swizzled tile images.
__global__ __launch_bounds__(256)
void convert_kernel(const float* __restrict__ out, int it) {
    const int t = blockIdx.x, b = blockIdx.y;
    const int tid = threadIdx.x;
    const float* xs = out + ((size_t)b * (ITERS + 1) + it) * (size_t)(D * N);
    unsigned char* ph = g_xh + (size_t)(b * NT + t) * IMG;
    unsigned char* pl = g_xl + (size_t)(b * NT + t) * IMG;
    #pragma unroll
    for (int q = 0; q < 4; ++q) {
        int task = q * 256 + tid;          // c(2) x d(64) x g(8)
        int c = task >> 9, rem = task & 511;
        int d = rem >> 3, g = rem & 7;
        int n0 = t * BN + c * 64 + g * 8;
        const float4* s = (const float4*)(xs + (size_t)d * N + n0);
        float4 v0 = s[0], v1 = s[1];
        uint32_t hp[4], lp[4];
        split_pair(v0.x, v0.y, hp[0], lp[0]);
        split_pair(v0.z, v0.w, hp[1], lp[1]);
        split_pair(v1.x, v1.y, hp[2], lp[2]);
        split_pair(v1.z, v1.w, hp[3], lp[3]);
        uint32_t off = c * 8192 + swz((uint32_t)(d * 128 + g * 16));
        *(uint4*)(ph + off) = make_uint4(hp[0], hp[1], hp[2], hp[3]);
        *(uint4*)(pl + off) = make_uint4(lp[0], lp[1], lp[2], lp[3]);
    }
}

// ---------------- main kernel ----------------
__global__ __launch_bounds__(THREADS, 1)
void ms_mma_kernel(float* __restrict__ out, int it) {
    extern __shared__ unsigned char smc[];
    uint32_t sb = smem_u32(smc);

    const int tid = threadIdx.x;
    const int l = tid & 31;
    const int w = tid >> 5;
    const int wm = w & 3;        // m group (32 rows)
    const int wn = w >> 2;       // n group (32 cols) / d group (16) in MMA2

    const int b = blockIdx.y;
    const int m0 = blockIdx.x * BM;
    const float* __restrict__ xin = out + ((size_t)b * (ITERS + 1) + it) * (size_t)(D * N);
    float* __restrict__ xout = (float*)xin + (size_t)D * N;

    const int l7 = l & 7, l8 = l & 8, l16h = (l & 16) >> 1, lq = l >> 2, lr = l & 3;

    // ---- prologue: async-load XM and XN(0) ----
    {
        const unsigned char* sh = g_xh + (size_t)(b * NT + blockIdx.x) * IMG;
        const unsigned char* sl = g_xl + (size_t)(b * NT + blockIdx.x) * IMG;
        cp16(sb + XM_H + tid * 16, sh + tid * 16);
        cp16(sb + XM_H + 8192 + tid * 16, sh + 8192 + tid * 16);
        cp16(sb + XM_L + tid * 16, sl + tid * 16);
        cp16(sb + XM_L + 8192 + tid * 16, sl + 8192 + tid * 16);
        const unsigned char* nh = g_xh + (size_t)(b * NT + 0) * IMG;
        const unsigned char* nl = g_xl + (size_t)(b * NT + 0) * IMG;
        cp16(sb + XN_BASE0 + tid * 16, nh + tid * 16);
        cp16(sb + XN_BASE0 + 8192 + tid * 16, nh + 8192 + tid * 16);
        cp16(sb + XN_BASE0 + 16384 + tid * 16, nl + tid * 16);
        cp16(sb + XN_BASE0 + 24576 + tid * 16, nl + 24576 - 16384 + tid * 16);
        CP_COMMIT();
    }

    float accO[2][2][4];
    #pragma unroll
    for (int i = 0; i < 2; ++i)
        #pragma unroll
        for (int j = 0; j < 2; ++j)
            #pragma unroll
            for (int c = 0; c < 4; ++c) accO[i][j][c] = 0.0f;

    float dsum[2][2] = {{0.0f, 0.0f}, {0.0f, 0.0f}};

    // address components reused every tile
    const int mchunk = (wm >> 1) * 8192;
    const int mloc = (wm & 1) * 32 + l8;           // + mi*16 (A, MMA1)
    const int nchunk = (wn >> 1) * 8192;
    const int nloc = (wn & 1) * 32 + l16h;         // + np*16 (B, MMA1)

    for (int t = 0; t < NT; ++t) {
        const uint32_t XNB = sb + ((t & 1) ? XN_BASE1 : XN_BASE0);
        // prefetch next tile into other buffer
        if (t + 1 < NT) {
            const uint32_t nb = sb + (((t + 1) & 1) ? XN_BASE1 : XN_BASE0);
            const unsigned char* nh = g_xh + (size_t)(b * NT + t + 1) * IMG;
            const unsigned char* nl = g_xl + (size_t)(b * NT + t + 1) * IMG;
            cp16(nb + tid * 16, nh + tid * 16);
            cp16(nb + 8192 + tid * 16, nh + 8192 + tid * 16);
            cp16(nb + 16384 + tid * 16, nl + tid * 16);
            cp16(nb + 24576 + tid * 16, nl + 8192 + tid * 16);
            CP_COMMIT();
            CP_WAIT1();
        } else {
            CP_WAIT0();
        }
        __syncthreads();

        // ---- MMA1: S[32m x 32n] per warp, k = 64 d, 3 split passes ----
        float accS[2][4][4];
        #pragma unroll
        for (int i = 0; i < 2; ++i)
            #pragma unroll
            for (int j = 0; j < 4; ++j)
                #pragma unroll
                for (int c = 0; c < 4; ++c) accS[i][j][c] = 0.0f;

        #pragma unroll
        for (int k = 0; k < 4; ++k) {
            const int kb = k * 16;
            uint32_t Ah[2][4], Al[2][4];
            const int drowA = kb + l7 + l16h;
            #pragma unroll
            for (int mi = 0; mi < 2; ++mi) {
                uint32_t off = swz((uint32_t)(drowA * 128 + (mloc + mi * 16) * 2)) + mchunk;
                LDSM_X4_T(Ah[mi], sb + XM_H + off);
                LDSM_X4_T(Al[mi], sb + XM_L + off);
            }
            const int drowB = kb + l7 + l8;
            #pragma unroll
            for (int np = 0; np < 2; ++np) {
                uint32_t Bh[4], Bl[4];
                uint32_t off = swz((uint32_t)(drowB * 128 + (nloc + np * 16) * 2)) + nchunk;
                LDSM_X4_T(Bh, XNB + off);
                LDSM_X4_T(Bl, XNB + 16384 + off);
                #pragma unroll
                for (int mi = 0; mi < 2; ++mi) {
                    hmma(accS[mi][2 * np],     Ah[mi], Bh);
                    hmma(accS[mi][2 * np + 1], Ah[mi], Bh + 2);
                    hmma(accS[mi][2 * np],     Ah[mi], Bl);
                    hmma(accS[mi][2 * np + 1], Ah[mi], Bl + 2);
                    hmma(accS[mi][2 * np],     Al[mi], Bh);
                    hmma(accS[mi][2 * np + 1], Al[mi], Bh + 2);
                }
            }
        }

        // ---- K = exp(KBW*S): den accumulation + K [m][n] hi/lo to smem ----
        #pragma unroll
        for (int mi = 0; mi < 2; ++mi) {
            const int m = wm * 32 + mi * 16 + lq;
            #pragma unroll
            for (int nj = 0; nj < 4; ++nj) {
                float e0 = expk(accS[mi][nj][0]);
                float e1 = expk(accS[mi][nj][1]);
                float e2 = expk(accS[mi][nj][2]);
                float e3 = expk(accS[mi][nj][3]);
                dsum[mi][0] += e0 + e1;
                dsum[mi][1] += e2 + e3;
                uint32_t h01, l01, h23, l23;
                split_pair(e0, e1, h01, l01);
                split_pair(e2, e3, h23, l23);
                int nit = wn * 32 + nj * 8 + 2 * lr;       // n within tile
                int kch = (nit >> 6) * 16384;
                int ncol = (nit & 63) * 2;
                uint32_t o1 = swz((uint32_t)(m * 128 + ncol)) + kch;
                uint32_t o2 = swz((uint32_t)((m + 8) * 128 + ncol)) + kch;
                STS32(sb + KT_H + o1, h01);
                STS32(sb + KT_L + o1, l01);
                STS32(sb + KT_H + o2, h23);
                STS32(sb + KT_L + o2, l23);
            }
        }
        __syncthreads();

        // ---- MMA2: O[32m x 16d] per warp += K . Xn^T, k = 128 n ----
        #pragma unroll
        for (int ks = 0; ks < 8; ++ks) {
            const int ch = ks >> 2;
            const int kb2 = (ks & 3) * 16;
            uint32_t Ah[2][4], Al[2][4];
            #pragma unroll
            for (int mi = 0; mi < 2; ++mi) {
                int m = wm * 32 + mi * 16 + (l & 15);
                uint32_t off = swz((uint32_t)(m * 128 + (kb2 + l16h) * 2)) + ch * 16384;
                LDSM_X4(Ah[mi], sb + KT_H + off);
                LDSM_X4(Al[mi], sb + KT_L + off);
            }
            uint32_t Bh[4], Bl[4];
            {
                int dd = wn * 16 + l7 + l16h;
                int ncol = kb2 + l8;                    // n within chunk
                uint32_t off = swz((uint32_t)(dd * 128 + ncol * 2)) + ch * 8192;
                LDSM_X4(Bh, XNB + off);
                LDSM_X4(Bl, XNB + 16384 + off);
            }
            #pragma unroll
            for (int mi = 0; mi < 2; ++mi) {
                hmma(accO[mi][0], Ah[mi], Bh);
                hmma(accO[mi][1], Ah[mi], Bh + 2);
                hmma(accO[mi][0], Ah[mi], Bl);
                hmma(accO[mi][1], Ah[mi], Bl + 2);
                hmma(accO[mi][0], Al[mi], Bh);
                hmma(accO[mi][1], Al[mi], Bh + 2);
            }
        }
        __syncthreads();   // KT / XN buffer reuse safe
    }

    // ---- reduce den: shfl over lr, then across 4 wn groups via smem ----
    float* sDen = (float*)(smc + SDEN);     // [4][128]
    #pragma unroll
    for (int mi = 0; mi < 2; ++mi)
        #pragma unroll
        for (int h = 0; h < 2; ++h) {
            float v = dsum[mi][h];
            v += __shfl_xor_sync(0xFFFFFFFFu, v, 1);
            v += __shfl_xor_sync(0xFFFFFFFFu, v, 2);
            if (lr == 0)
                sDen[wn * 128 + wm * 32 + mi * 16 + h * 8 + lq] = v;
        }
    __syncthreads();

    // ---- O epilogue: scale by STEP/den, transpose via smem ----
    float* sO = (float*)(smc + KT_H);   // [64 dd][132 m]
    float sc[2][2];
    #pragma unroll
    for (int mi = 0; mi < 2; ++mi)
        #pragma unroll
        for (int h = 0; h < 2; ++h) {
            int m = wm * 32 + mi * 16 + h * 8 + lq;
            sc[mi][h] = STEP / (sDen[m] + sDen[128 + m] + sDen[256 + m] + sDen[384 + m]);
        }
    __syncthreads();   // sDen read before sO (overlapping? no: sO reuses KT, sDen separate) -- keep ordering safe
    #pragma unroll
    for (int mi = 0; mi < 2; ++mi) {
        int m = wm * 32 + mi * 16 + lq;
        #pragma unroll
        for (int dj = 0; dj < 2; ++dj) {
            int dd = wn * 16 + dj * 8 + 2 * lr;
            sO[dd * 132 + m]           = accO[mi][dj][0] * sc[mi][0];
            sO[(dd + 1) * 132 + m]     = accO[mi][dj][1] * sc[mi][0];
            sO[dd * 132 + m + 8]       = accO[mi][dj][2] * sc[mi][1];
            sO[(dd + 1) * 132 + m + 8] = accO[mi][dj][3] * sc[mi][1];
        }
    }
    __syncthreads();

    #pragma unroll
    for (int q = 0; q < 4; ++q) {
        int task = q * THREADS + tid;       // dd(64) x mq(32)
        int dd = task >> 5, mq = task & 31;
        float4 o = *(float4*)&sO[dd * 132 + mq * 4];
        float4 x = *(const float4*)(xin + (size_t)dd * N + m0 + mq * 4);
        float4 r;
        r.x = fmaf(1.0f - STEP, x.x, o.x);
        r.y = fmaf(1.0f - STEP, x.y, o.y);
        r.z = fmaf(1.0f - STEP, x.z, o.z);
        r.w = fmaf(1.0f - STEP, x.w, o.w);
        *(float4*)(xout + (size_t)dd * N + m0 + mq * 4) = r;
    }
}

extern "C" void kernel_launch(void* const* d_in, const int* in_sizes, int n_in,
                              void* d_out, int out_size) {
    const float* x = (const float*)d_in[0];
    float* out = (float*)d_out;

    cudaFuncSetAttribute(ms_mma_kernel,
                         cudaFuncAttributeMaxDynamicSharedMemorySize, SMEM_BYTES);

    int copy_total = B * D * N / 4;
    copy_x0_kernel<<<(copy_total + 255) / 256, 256>>>(x, out);

    dim3 cgrid(NT, B);
    dim3 grid(NT, B);
    for (int it = 0; it < ITERS; ++it) {
        convert_kernel<<<cgrid, 256>>>(out, it);
        ms_mma_kernel<<<grid, THREADS, SMEM_BYTES>>>(out, it);
    }
}

// round 5
// speedup vs baseline: 3.6673x; 1.1712x over previous
#include <cuda_runtime.h>
#include <cuda_bf16.h>
#include <cstdint>

// ---------------- problem constants ----------------
constexpr int B = 2;
constexpr int D = 64;
constexpr int N = 96 * 96;      // 9216
constexpr int ITERS = 4;
constexpr float STEP = 0.5f;
constexpr float KBW = 0.3f;

constexpr int BM = 128;
constexpr int BN = 128;
constexpr int THREADS = 512;
constexpr int NT = N / BN;      // 72

// Tile image: 2 chunks x [64 d][64 pt] bf16, 128B swizzled rows = 16384 B
constexpr int IMG = 16384;

__device__ __align__(16) unsigned char g_xh[(size_t)B * NT * IMG];
__device__ __align__(16) unsigned char g_xl[(size_t)B * NT * IMG];

// ---------------- smem layout (bytes) ----------------
constexpr int XM_H = 0;              // 16 KB
constexpr int XM_L = 16384;
constexpr int XN0  = 32768;          // H +0, L +16384 (32 KB)
constexpr int XN1  = 65536;
constexpr int SDEN = 98304;          // 256 f32
constexpr int MBAR = 99360;          // 3 mbarriers
constexpr int SMEM_BYTES = 99392;
// epilogue reuse: sO0 f32[64][132] at 0, sO1 at 33792 (after final barrier)

// ---------------- asm helpers ----------------
__device__ __forceinline__ uint32_t smem_u32(const void* p) {
    uint32_t a;
    asm("{ .reg .u64 t; cvta.to.shared.u64 t, %1; cvt.u32.u64 %0, t; }"
        : "=r"(a) : "l"(p));
    return a;
}

__device__ __forceinline__ uint32_t swz(uint32_t o) {
    return o ^ ((o >> 3) & 0x70);
}

#define MBAR_INIT(mbar, cnt) \
    asm volatile("mbarrier.init.shared.b64 [%0], %1;" :: "r"(mbar), "r"(cnt) : "memory")

#define MBAR_EXPECT_TX(mbar, bytes) \
    asm volatile("mbarrier.arrive.expect_tx.shared.b64 _, [%0], %1;" \
                 :: "r"(mbar), "r"(bytes) : "memory")

#define MBAR_WAIT(mbar, parity) do {                                          \
    uint32_t _m = (mbar), _p = (parity);                                      \
    asm volatile(                                                             \
        "{\n\t.reg .pred P1;\n\t"                                             \
        "WAIT_LOOP_%=:\n\t"                                                   \
        "mbarrier.try_wait.parity.acquire.cta.shared::cta.b64 P1, [%0], %1, 0x989680;\n\t" \
        "@P1 bra.uni WAIT_DONE_%=;\n\t"                                       \
        "bra.uni WAIT_LOOP_%=;\n\t"                                           \
        "WAIT_DONE_%=:\n\t}"                                                  \
        :: "r"(_m), "r"(_p) : "memory");                                      \
} while (0)

__device__ __forceinline__ void bulk_g2s(uint32_t dst, const void* src,
                                         uint32_t bytes, uint32_t mbar) {
    asm volatile(
        "cp.async.bulk.shared::cluster.global.mbarrier::complete_tx::bytes "
        "[%0], [%1], %2, [%3];"
        :: "r"(dst), "l"(__cvta_generic_to_global(src)), "r"(bytes), "r"(mbar)
        : "memory");
}

#define LDSM_X4(r, addr)                                                     \
    asm volatile("ldmatrix.sync.aligned.m8n8.x4.shared.b16 {%0,%1,%2,%3}, [%4];" \
        : "=r"((r)[0]), "=r"((r)[1]), "=r"((r)[2]), "=r"((r)[3]) : "r"(addr))

#define LDSM_X4_T(r, addr)                                                   \
    asm volatile("ldmatrix.sync.aligned.m8n8.x4.trans.shared.b16 {%0,%1,%2,%3}, [%4];" \
        : "=r"((r)[0]), "=r"((r)[1]), "=r"((r)[2]), "=r"((r)[3]) : "r"(addr))

__device__ __forceinline__ void hmma(float* c, const uint32_t* a, const uint32_t* b) {
    asm volatile(
        "mma.sync.aligned.m16n8k16.row.col.f32.bf16.bf16.f32 "
        "{%0,%1,%2,%3}, {%4,%5,%6,%7}, {%8,%9}, {%0,%1,%2,%3};"
        : "+f"(c[0]), "+f"(c[1]), "+f"(c[2]), "+f"(c[3])
        : "r"(a[0]), "r"(a[1]), "r"(a[2]), "r"(a[3]), "r"(b[0]), "r"(b[1]));
}

__device__ __forceinline__ uint32_t pack_bf2(float hi, float lo) {
    uint32_t r;
    asm("cvt.rn.bf16x2.f32 %0, %1, %2;" : "=r"(r) : "f"(hi), "f"(lo));
    return r;
}

__device__ __forceinline__ uint32_t pack2(__nv_bfloat16 a, __nv_bfloat16 b) {
    return (uint32_t)__bfloat16_as_ushort(a) |
           ((uint32_t)__bfloat16_as_ushort(b) << 16);
}

__device__ __forceinline__ void split_pair(float v0, float v1,
                                           uint32_t& hw, uint32_t& lw) {
    __nv_bfloat16 h0 = __float2bfloat16_rn(v0);
    __nv_bfloat16 h1 = __float2bfloat16_rn(v1);
    __nv_bfloat16 l0 = __float2bfloat16_rn(v0 - __bfloat162float(h0));
    __nv_bfloat16 l1 = __float2bfloat16_rn(v1 - __bfloat162float(h1));
    hw = pack2(h0, h1);
    lw = pack2(l0, l1);
}

// exp(KBW*s): fma-pipe polynomial 2^t with exponent splice
__device__ __forceinline__ float expk(float s) {
    const float C = KBW * 1.4426950408889634f;
    float t = s * C;
    float r = t + 12582912.0f;
    int ii = __float_as_int(r) - 0x4B400000;
    float f = t - (r - 12582912.0f);
    float p = 1.3333558146428443e-3f;
    p = fmaf(p, f, 9.618129107628477e-3f);
    p = fmaf(p, f, 5.550410866482158e-2f);
    p = fmaf(p, f, 2.402265069591007e-1f);
    p = fmaf(p, f, 6.931471805599453e-1f);
    p = fmaf(p, f, 1.0f);
    return __int_as_float(__float_as_int(p) + (ii << 23));
}

// Copy x_in (B, D, N) into output slice i=0 of (B, ITERS+1, D, N)
__global__ void copy_x0_kernel(const float* __restrict__ x, float* __restrict__ out) {
    int i = blockIdx.x * blockDim.x + threadIdx.x;
    int total = B * D * N / 4;
    if (i < total) {
        int perb = D * N / 4;
        int b = i / perb;
        int r = i - b * perb;
        float4 v = ((const float4*)x)[i];
        ((float4*)out)[(size_t)b * ((ITERS + 1) * D * N / 4) + r] = v;
    }
}

// Convert x slice `it` into hi/lo bf16 swizzled tile images.
__global__ __launch_bounds__(256)
void convert_kernel(const float* __restrict__ out, int it) {
    const int t = blockIdx.x, b = blockIdx.y;
    const int tid = threadIdx.x;
    const float* xs = out + ((size_t)b * (ITERS + 1) + it) * (size_t)(D * N);
    unsigned char* ph = g_xh + (size_t)(b * NT + t) * IMG;
    unsigned char* pl = g_xl + (size_t)(b * NT + t) * IMG;
    #pragma unroll
    for (int q = 0; q < 4; ++q) {
        int task = q * 256 + tid;          // c(2) x d(64) x g(8)
        int c = task >> 9, rem = task & 511;
        int d = rem >> 3, g = rem & 7;
        int n0 = t * BN + c * 64 + g * 8;
        const float4* s = (const float4*)(xs + (size_t)d * N + n0);
        float4 v0 = s[0], v1 = s[1];
        uint32_t hp[4], lp[4];
        split_pair(v0.x, v0.y, hp[0], lp[0]);
        split_pair(v0.z, v0.w, hp[1], lp[1]);
        split_pair(v1.x, v1.y, hp[2], lp[2]);
        split_pair(v1.z, v1.w, hp[3], lp[3]);
        uint32_t off = c * 8192 + swz((uint32_t)(d * 128 + g * 16));
        *(uint4*)(ph + off) = make_uint4(hp[0], hp[1], hp[2], hp[3]);
        *(uint4*)(pl + off) = make_uint4(lp[0], lp[1], lp[2], lp[3]);
    }
}

// ---------------- main kernel ----------------
__global__ __launch_bounds__(THREADS, 1)
void ms_mma_kernel(float* __restrict__ out, int it) {
    extern __shared__ unsigned char smc[];
    uint32_t sb = smem_u32(smc);

    const int tid = threadIdx.x;
    const int l = tid & 31;
    const int w = tid >> 5;
    const int wm = w >> 1;       // 8 m-groups of 16 rows
    const int wn = w & 1;        // 2 n-groups of 64 cols

    const int b = blockIdx.y;
    const int m0 = blockIdx.x * BM;
    const float* __restrict__ xin = out + ((size_t)b * (ITERS + 1) + it) * (size_t)(D * N);
    float* __restrict__ xout = (float*)xin + (size_t)D * N;

    const int l7 = l & 7, l8 = l & 8, l16h = (l & 16) >> 1, lq = l >> 2, lr = l & 3;

    const uint32_t mb0 = sb + MBAR, mb1 = sb + MBAR + 8, mbx = sb + MBAR + 16;

    // ---- prologue: mbarriers + bulk loads of XM and XN(0) ----
    if (tid == 0) {
        MBAR_INIT(mb0, 1);
        MBAR_INIT(mb1, 1);
        MBAR_INIT(mbx, 1);
    }
    __syncthreads();
    if (tid == 0) {
        const unsigned char* mh = g_xh + (size_t)(b * NT + blockIdx.x) * IMG;
        const unsigned char* ml = g_xl + (size_t)(b * NT + blockIdx.x) * IMG;
        MBAR_EXPECT_TX(mbx, 2 * IMG);
        bulk_g2s(sb + XM_H, mh, IMG, mbx);
        bulk_g2s(sb + XM_L, ml, IMG, mbx);
        const unsigned char* nh = g_xh + (size_t)(b * NT + 0) * IMG;
        const unsigned char* nl = g_xl + (size_t)(b * NT + 0) * IMG;
        MBAR_EXPECT_TX(mb0, 2 * IMG);
        bulk_g2s(sb + XN0, nh, IMG, mb0);
        bulk_g2s(sb + XN0 + IMG, nl, IMG, mb0);
    }

    // per-tile address components
    const int mchunk = (wm >> 2) * 8192;
    const int mcol = (wm & 3) * 16 + l8;          // within-chunk m for A (MMA1)
    const int nchunk = wn * 8192;                 // chunk for B (both MMAs)

    float accO[8][4];
    #pragma unroll
    for (int j = 0; j < 8; ++j)
        #pragma unroll
        for (int c = 0; c < 4; ++c) accO[j][c] = 0.0f;
    float dsum0 = 0.0f, dsum1 = 0.0f;

    MBAR_WAIT(mbx, 0);
    uint32_t p0 = 0, p1 = 0;

    for (int t = 0; t < NT; ++t) {
        const int buf = t & 1;
        const uint32_t XNB = sb + (buf ? XN1 : XN0);
        if (buf) { MBAR_WAIT(mb1, p1); p1 ^= 1; }
        else     { MBAR_WAIT(mb0, p0); p0 ^= 1; }
        __syncthreads();   // all warps past tile t-1 -> other buffer reusable
        if (tid == 0 && t + 1 < NT) {
            const uint32_t nb = sb + ((t + 1) & 1 ? XN1 : XN0);
            const uint32_t mbn = ((t + 1) & 1) ? mb1 : mb0;
            const unsigned char* nh = g_xh + (size_t)(b * NT + t + 1) * IMG;
            const unsigned char* nl = g_xl + (size_t)(b * NT + t + 1) * IMG;
            MBAR_EXPECT_TX(mbn, 2 * IMG);
            bulk_g2s(nb, nh, IMG, mbn);
            bulk_g2s(nb + IMG, nl, IMG, mbn);
        }

        // ---- MMA1: S[16m x 64n] per warp, k = 64 d, 3 split passes ----
        float accS[8][4];
        #pragma unroll
        for (int j = 0; j < 8; ++j)
            #pragma unroll
            for (int c = 0; c < 4; ++c) accS[j][c] = 0.0f;

        #pragma unroll
        for (int k = 0; k < 4; ++k) {
            const int kb = k * 16;
            uint32_t Ah[4], Al[4];
            const uint32_t offA =
                swz((uint32_t)((kb + l7 + l16h) * 128 + mcol * 2)) + mchunk;
            LDSM_X4_T(Ah, sb + XM_H + offA);
            LDSM_X4_T(Al, sb + XM_L + offA);
            const int drowB = kb + l7 + l8;
            #pragma unroll
            for (int np = 0; np < 4; ++np) {
                uint32_t Bh[4], Bl[4];
                const uint32_t offB =
                    swz((uint32_t)(drowB * 128 + (np * 16 + l16h) * 2)) + nchunk;
                LDSM_X4_T(Bh, XNB + offB);
                LDSM_X4_T(Bl, XNB + IMG + offB);
                hmma(accS[2 * np],     Ah, Bh);
                hmma(accS[2 * np + 1], Ah, Bh + 2);
                hmma(accS[2 * np],     Ah, Bl);
                hmma(accS[2 * np + 1], Ah, Bl + 2);
                hmma(accS[2 * np],     Al, Bh);
                hmma(accS[2 * np + 1], Al, Bh + 2);
            }
        }

        // ---- K = exp(KBW*S) in-register -> MMA2 A fragments (hi/lo) ----
        uint32_t AKh[4][4], AKl[4][4];
        #pragma unroll
        for (int nj = 0; nj < 8; ++nj) {
            float e0 = expk(accS[nj][0]);
            float e1 = expk(accS[nj][1]);
            float e2 = expk(accS[nj][2]);
            float e3 = expk(accS[nj][3]);
            dsum0 += e0 + e1;
            dsum1 += e2 + e3;
            uint32_t h01 = pack_bf2(e1, e0);     // low half = e0 (k=2t)
            uint32_t h23 = pack_bf2(e3, e2);
            float f0 = e0 - __int_as_float(h01 << 16);
            float f1 = e1 - __int_as_float(h01 & 0xFFFF0000u);
            float f2 = e2 - __int_as_float(h23 << 16);
            float f3 = e3 - __int_as_float(h23 & 0xFFFF0000u);
            uint32_t l01 = pack_bf2(f1, f0);
            uint32_t l23 = pack_bf2(f3, f2);
            const int ks = nj >> 1, r0 = (nj & 1) * 2;
            AKh[ks][r0] = h01;  AKh[ks][r0 + 1] = h23;
            AKl[ks][r0] = l01;  AKl[ks][r0 + 1] = l23;
        }

        // ---- MMA2: O[16m x 64d] per warp += K(regs) . Xn, k = 64 n-slice ----
        #pragma unroll
        for (int ks = 0; ks < 4; ++ks) {
            const int kcol = ks * 16 + l8;
            #pragma unroll
            for (int dg = 0; dg < 4; ++dg) {
                const int dd = dg * 16 + l7 + l16h;
                const uint32_t off =
                    swz((uint32_t)(dd * 128 + kcol * 2)) + nchunk;
                uint32_t Bh[4], Bl[4];
                LDSM_X4(Bh, XNB + off);
                LDSM_X4(Bl, XNB + IMG + off);
                hmma(accO[2 * dg],     AKh[ks], Bh);
                hmma(accO[2 * dg + 1], AKh[ks], Bh + 2);
                hmma(accO[2 * dg],     AKh[ks], Bl);
                hmma(accO[2 * dg + 1], AKh[ks], Bl + 2);
                hmma(accO[2 * dg],     AKl[ks], Bh);
                hmma(accO[2 * dg + 1], AKl[ks], Bh + 2);
            }
        }
    }

    // ---- den reduction: shfl over lane pair bits, write per n-group ----
    float* sDen = (float*)(smc + SDEN);     // [2][128]
    {
        float v0 = dsum0, v1 = dsum1;
        v0 += __shfl_xor_sync(0xFFFFFFFFu, v0, 1);
        v0 += __shfl_xor_sync(0xFFFFFFFFu, v0, 2);
        v1 += __shfl_xor_sync(0xFFFFFFFFu, v1, 1);
        v1 += __shfl_xor_sync(0xFFFFFFFFu, v1, 2);
        if (lr == 0) {
            sDen[wn * 128 + wm * 16 + lq] = v0;
            sDen[wn * 128 + wm * 16 + 8 + lq] = v1;
        }
    }
    __syncthreads();   // sDen visible; all warps done with XN buffers

    // ---- partial-O epilogue: scale by STEP/den, write per n-group region ----
    const int mA = wm * 16 + lq, mB = mA + 8;
    const float scA = STEP / (sDen[mA] + sDen[128 + mA]);
    const float scB = STEP / (sDen[mB] + sDen[128 + mB]);
    float* sO = (float*)(smc + wn * 33792);   // [64 d][132 m]
    #pragma unroll
    for (int dg = 0; dg < 4; ++dg)
        #pragma unroll
        for (int s = 0; s < 2; ++s) {
            const float* c = accO[2 * dg + s];
            const int dbase = dg * 16 + s * 8 + 2 * lr;
            sO[dbase * 132 + mA]       = c[0] * scA;
            sO[(dbase + 1) * 132 + mA] = c[1] * scA;
            sO[dbase * 132 + mB]       = c[2] * scB;
            sO[(dbase + 1) * 132 + mB] = c[3] * scB;
        }
    __syncthreads();

    // ---- combine partials + blend with x, store ----
    const float* sO0 = (const float*)(smc);
    const float* sO1 = (const float*)(smc + 33792);
    #pragma unroll
    for (int q = 0; q < 4; ++q) {
        int task = q * THREADS + tid;       // dd(64) x mq(32)
        int dd = task >> 5, mq = task & 31;
        float4 o0 = *(const float4*)&sO0[dd * 132 + mq * 4];
        float4 o1 = *(const float4*)&sO1[dd * 132 + mq * 4];
        float4 x = *(const float4*)(xin + (size_t)dd * N + m0 + mq * 4);
        float4 r;
        r.x = fmaf(1.0f - STEP, x.x, o0.x + o1.x);
        r.y = fmaf(1.0f - STEP, x.y, o0.y + o1.y);
        r.z = fmaf(1.0f - STEP, x.z, o0.z + o1.z);
        r.w = fmaf(1.0f - STEP, x.w, o0.w + o1.w);
        *(float4*)(xout + (size_t)dd * N + m0 + mq * 4) = r;
    }
}

extern "C" void kernel_launch(void* const* d_in, const int* in_sizes, int n_in,
                              void* d_out, int out_size) {
    const float* x = (const float*)d_in[0];
    float* out = (float*)d_out;

    cudaFuncSetAttribute(ms_mma_kernel,
                         cudaFuncAttributeMaxDynamicSharedMemorySize, SMEM_BYTES);

    int copy_total = B * D * N / 4;
    copy_x0_kernel<<<(copy_total + 255) / 256, 256>>>(x, out);

    dim3 grid(NT, B);
    for (int it = 0; it < ITERS; ++it) {
        convert_kernel<<<grid, 256>>>(out, it);
        ms_mma_kernel<<<grid, THREADS, SMEM_BYTES>>>(out, it);
    }
}